// round 15
// baseline (speedup 1.0000x reference)
#include <cuda_runtime.h>
#include <cuda_bf16.h>
#include <math.h>
#include <stdint.h>

// Problem dims (fixed by setup_inputs): B=2, S=2048, H=2048, I=8192
#define MTOK 4096
#define HDIM 2048
#define IDIM 8192
#define NGU  16384

// ---------------- scratch (static __device__ globals; device-side use ONLY) --------
__device__ double g_part1[4096];
__device__ double g_part2[2048];
__device__ float  g_consts[4];                           // {s1, 1/s1, s2, 1/s2}
__device__ __nv_bfloat16 g_w1q[(size_t)NGU  * HDIM];     // gate/up row-interleaved
__device__ __nv_bfloat16 g_w2q[(size_t)HDIM * IDIM];
__device__ __nv_bfloat16 g_a1q[(size_t)MTOK * HDIM];
__device__ __nv_bfloat16 g_a2q[(size_t)MTOK * IDIM];
__device__ float g_a1dq[MTOK];
__device__ float g_a2dq[MTOK];
__device__ float g_s[(size_t)MTOK * IDIM];               // silu(gate)*up, f32

__device__ __forceinline__ uint32_t s2u(const void* p) {
    uint32_t a;
    asm("{ .reg .u64 t; cvta.to.shared.u64 t, %1; cvt.u32.u64 %0, t; }" : "=r"(a) : "l"(p));
    return a;
}

#define MMAB16(c, a0, a1, a2, a3, b0, b1) \
    asm volatile("mma.sync.aligned.m16n8k16.row.col.f32.bf16.bf16.f32 " \
                 "{%0,%1,%2,%3}, {%4,%5,%6,%7}, {%8,%9}, {%0,%1,%2,%3};" \
                 : "+f"((c)[0]), "+f"((c)[1]), "+f"((c)[2]), "+f"((c)[3]) \
                 : "r"(a0), "r"(a1), "r"(a2), "r"(a3), "r"(b0), "r"(b1))

#define LDSM4(r, addr) \
    asm volatile("ldmatrix.sync.aligned.m8n8.x4.shared.b16 {%0,%1,%2,%3}, [%4];" \
                 : "=r"((r)[0]), "=r"((r)[1]), "=r"((r)[2]), "=r"((r)[3]) : "r"(addr))

#define CP16(dst, src) \
    asm volatile("cp.async.cg.shared.global [%0], [%1], 16;" \
                 :: "r"(dst), "l"(__cvta_generic_to_global(src)) : "memory")
#define CP_COMMIT() asm volatile("cp.async.commit_group;" ::: "memory")
#define CP_WAIT1()  asm volatile("cp.async.wait_group 1;" ::: "memory")

// ======================= elementwise kernels (proven) =======================
__global__ void k_abspart(const float* __restrict__ wg, const float* __restrict__ wd) {
    const float* w;
    double* part;
    int bi;
    if (blockIdx.x < 4096) { w = wg; part = g_part1; bi = blockIdx.x; }
    else                   { w = wd; part = g_part2; bi = blockIdx.x - 4096; }
    size_t base = (size_t)bi * 8192 + (size_t)threadIdx.x * 4;
    double acc = 0.0;
#pragma unroll
    for (int j = 0; j < 8; j++) {
        float4 v = *reinterpret_cast<const float4*>(w + base + (size_t)j * 1024);
        acc += (double)fabsf(v.x) + (double)fabsf(v.y) +
               (double)fabsf(v.z) + (double)fabsf(v.w);
    }
    __shared__ double sm[256];
    sm[threadIdx.x] = acc;
    __syncthreads();
    for (int s = 128; s > 0; s >>= 1) {
        if (threadIdx.x < s) sm[threadIdx.x] += sm[threadIdx.x + s];
        __syncthreads();
    }
    if (threadIdx.x == 0) part[bi] = sm[0];
}

__global__ void k_finalize() {
    __shared__ double sm[256];
    int t = threadIdx.x;
    double a = 0.0;
    for (int i = t; i < 4096; i += 256) a += g_part1[i];
    sm[t] = a; __syncthreads();
    for (int s = 128; s > 0; s >>= 1) { if (t < s) sm[t] += sm[t + s]; __syncthreads(); }
    double sum1 = sm[0];
    __syncthreads();
    double b = 0.0;
    for (int i = t; i < 2048; i += 256) b += g_part2[i];
    sm[t] = b; __syncthreads();
    for (int s = 128; s > 0; s >>= 1) { if (t < s) sm[t] += sm[t + s]; __syncthreads(); }
    if (t == 0) {
        float m1 = (float)(sum1 / (double)((size_t)NGU * HDIM));
        float s1 = 1.0f / fmaxf(m1, 1e-5f);
        g_consts[0] = s1; g_consts[1] = 1.0f / s1;
        float m2 = (float)(sm[0] / (double)((size_t)HDIM * IDIM));
        float s2 = 1.0f / fmaxf(m2, 1e-5f);
        g_consts[2] = s2; g_consts[3] = 1.0f / s2;
    }
}

// fused: blocks [0,49152) weight ternarization; [49152,53248) rmsnorm+actquant stage1
__global__ void k_quant_act(const float* __restrict__ wg, const float* __restrict__ wd,
                            const float* __restrict__ x,  const float* __restrict__ gg) {
    __shared__ float sm[256];
    const unsigned NBW = 49152;
    const unsigned NB1 = ((unsigned)NGU * HDIM) / 1024;   // 32768

    if (blockIdx.x < NBW) {
        const float* w;
        __nv_bfloat16* wq;
        float scale;
        size_t isrc, idst;
        if (blockIdx.x < NB1) {
            w = wg; wq = g_w1q; scale = g_consts[0];
            isrc = ((size_t)blockIdx.x * 256 + threadIdx.x) * 4;
            size_t row = isrc / HDIM;
            size_t col = isrc % HDIM;
            size_t drow = (row < IDIM) ? (2 * row) : (2 * (row - IDIM) + 1);
            idst = drow * HDIM + col;
        } else {
            w = wd; wq = g_w2q; scale = g_consts[2];
            isrc = ((size_t)(blockIdx.x - NB1) * 256 + threadIdx.x) * 4;
            idst = isrc;
        }
        float4 v = *reinterpret_cast<const float4*>(w + isrc);
        __nv_bfloat162 p0, p1;
        p0.x = __float2bfloat16(fminf(fmaxf(rintf(v.x * scale), -1.0f), 1.0f));
        p0.y = __float2bfloat16(fminf(fmaxf(rintf(v.y * scale), -1.0f), 1.0f));
        p1.x = __float2bfloat16(fminf(fmaxf(rintf(v.z * scale), -1.0f), 1.0f));
        p1.y = __float2bfloat16(fminf(fmaxf(rintf(v.w * scale), -1.0f), 1.0f));
        uint2 pk;
        pk.x = *reinterpret_cast<uint32_t*>(&p0);
        pk.y = *reinterpret_cast<uint32_t*>(&p1);
        *reinterpret_cast<uint2*>(wq + idst) = pk;
    } else {
        int m = blockIdx.x - NBW, t = threadIdx.x;
        const float* xr = x + (size_t)m * HDIM;
        float v[8]; float ss = 0.0f;
#pragma unroll
        for (int j = 0; j < 8; j++) { v[j] = xr[t + j * 256]; ss += v[j] * v[j]; }
        sm[t] = ss; __syncthreads();
        for (int s = 128; s > 0; s >>= 1) { if (t < s) sm[t] += sm[t + s]; __syncthreads(); }
        float var = sm[0] * (1.0f / (float)HDIM);
        __syncthreads();
        float r = 1.0f / sqrtf(var + 1e-8f);
        float h[8]; float am = 0.0f;
#pragma unroll
        for (int j = 0; j < 8; j++) {
            h[j] = (v[j] * r) * gg[t + j * 256];
            am = fmaxf(am, fabsf(h[j]));
        }
        sm[t] = am; __syncthreads();
        for (int s = 128; s > 0; s >>= 1) { if (t < s) sm[t] = fmaxf(sm[t], sm[t + s]); __syncthreads(); }
        float qs = 127.0f / fmaxf(sm[0], 1e-5f);
        __nv_bfloat16* aq = g_a1q + (size_t)m * HDIM;
#pragma unroll
        for (int j = 0; j < 8; j++) {
            float q = fminf(fmaxf(rintf(h[j] * qs), -128.0f), 127.0f);
            aq[t + j * 256] = __float2bfloat16(q);
        }
        if (t == 0) g_a1dq[m] = 1.0f / qs;
    }
}

// stage-2: reads precomputed s = silu(gate)*up; rmsnorm(g_down) + quant
__global__ void k_actq2(const float* __restrict__ gdown) {
    __shared__ float sm[256];
    int m = blockIdx.x, t = threadIdx.x;
    const float* sr = g_s + (size_t)m * IDIM;
    float s[32]; float ss = 0.0f;
#pragma unroll
    for (int j = 0; j < 32; j++) {
        float sv = sr[t + j * 256];
        s[j] = sv; ss += sv * sv;
    }
    sm[t] = ss; __syncthreads();
    for (int st = 128; st > 0; st >>= 1) { if (t < st) sm[t] += sm[t + st]; __syncthreads(); }
    float var = sm[0] * (1.0f / (float)IDIM);
    __syncthreads();
    float r = 1.0f / sqrtf(var + 1e-8f);
    float am = 0.0f;
#pragma unroll
    for (int j = 0; j < 32; j++) {
        s[j] = (s[j] * r) * gdown[t + j * 256];
        am = fmaxf(am, fabsf(s[j]));
    }
    sm[t] = am; __syncthreads();
    for (int st = 128; st > 0; st >>= 1) { if (t < st) sm[t] = fmaxf(sm[t], sm[t + st]); __syncthreads(); }
    float qs = 127.0f / fmaxf(sm[0], 1e-5f);
    __nv_bfloat16* aq = g_a2q + (size_t)m * IDIM;
#pragma unroll
    for (int j = 0; j < 32; j++) {
        float q = fminf(fmaxf(rintf(s[j] * qs), -128.0f), 127.0f);
        aq[t + j * 256] = __float2bfloat16(q);
    }
    if (t == 0) g_a2dq[m] = 1.0f / qs;
}

// ======================= bf16 HMMA GEMM v8: A-fragment software pipeline ===========
// R14 (proven: KCE=64 SW128, 128thr/CTA, 64x64 warp tiles, 2 CTAs/SM) with the one
// structural fix the 75%-tensor profile demanded: LDSM4(a[mt+1]) issues BEFORE the
// 8 MMAs consuming a[mt], hiding the ~29cyc LDS latency under 64 MMA cycles.
#define KCE 64
#define TILE_BYTES 16384                    // 128 rows x 128B per operand
#define STAGE_BYTES (2 * TILE_BYTES)        // 32768
#define NSTAGE 3
#define GEMM_SMEM (NSTAGE * STAGE_BYTES)    // 98304

__global__ __launch_bounds__(128, 2) void k_gemm_mma(int which, float* __restrict__ outp) {
    const __nv_bfloat16* A;
    const __nv_bfloat16* W;
    const float* adq;
    float wrec;
    int N, K;
    if (which == 0) {
        A = g_a1q; W = g_w1q; adq = g_a1dq;
        wrec = g_consts[1]; N = NGU; K = HDIM;
    } else {
        A = g_a2q; W = g_w2q; adq = g_a2dq;
        wrec = g_consts[3]; N = HDIM; K = IDIM;
    }

    extern __shared__ __align__(16) char smbuf[];
    const uint32_t sbase = s2u(smbuf);

    const int tid  = threadIdx.x;
    const int lane = tid & 31;
    const int warp = tid >> 5;
    const int wm   = warp >> 1;             // 0..1 (M)
    const int wn   = warp & 1;              // 0..1 (N)
    const int g    = lane >> 2;
    const int tig  = lane & 3;
    const int rowbase = blockIdx.y * 128;
    const int colbase = blockIdx.x * 128;

    // ---- cp.async loader: 16 x 16B per thread per chunk (8 passes x A,B) ----
    const int lr8 = tid >> 3;               // 0..15 (row within pass)
    const int lc8 = tid & 7;                // 16B column 0..7
    uint32_t dstA[8], dstB[8];
    const __nv_bfloat16* srcA[8];
    const __nv_bfloat16* srcB[8];
#pragma unroll
    for (int p = 0; p < 8; p++) {
        int r = p * 16 + lr8;
        uint32_t off = (uint32_t)(r * 128 + ((lc8 ^ (r & 7)) * 16));
        dstA[p] = off;
        dstB[p] = TILE_BYTES + off;
        srcA[p] = A + (size_t)(rowbase + r) * K + lc8 * 8;
        srcB[p] = W + (size_t)(colbase + r) * K + lc8 * 8;
    }

    // ---- ldmatrix lane addressing (R13/R14-proven swizzle formulas) ----
    const uint32_t m8  = (uint32_t)(lane & 7);
    const uint32_t aRB = (uint32_t)((wm * 64 + (lane & 15)) * 128);
    const uint32_t ahi = (uint32_t)(lane >> 4);
    const uint32_t bRB = (uint32_t)(TILE_BYTES +
                          (wn * 64 + ((lane >> 4) & 1) * 8 + (lane & 7)) * 128);
    const uint32_t bhi = (uint32_t)((lane >> 3) & 1);

    uint32_t acs[4], bcs[4];
#pragma unroll
    for (int k = 0; k < 4; k++) {
        acs[k] = ((2u * k + ahi) ^ m8) * 16u;
        bcs[k] = ((2u * k + bhi) ^ m8) * 16u;
    }

    float acc[4][8][4];
#pragma unroll
    for (int i = 0; i < 4; i++)
#pragma unroll
        for (int j = 0; j < 8; j++)
#pragma unroll
            for (int q = 0; q < 4; q++) acc[i][j][q] = 0.0f;

    const int nk = K / KCE;

    // ---- prologue: stage chunks 0,1 ----
#pragma unroll
    for (int s = 0; s < 2; s++) {
        uint32_t d = sbase + s * STAGE_BYTES;
        int ko = s * KCE;
#pragma unroll
        for (int p = 0; p < 8; p++) {
            CP16(d + dstA[p], srcA[p] + ko);
            CP16(d + dstB[p], srcB[p] + ko);
        }
        CP_COMMIT();
    }

    int stage = 0;
    for (int kt = 0; kt < nk; kt++) {
        CP_WAIT1();
        __syncthreads();

        if (kt + 2 < nk) {
            int rs = stage + 2; if (rs >= NSTAGE) rs -= NSTAGE;
            uint32_t d = sbase + rs * STAGE_BYTES;
            int ko = (kt + 2) * KCE;
#pragma unroll
            for (int p = 0; p < 8; p++) {
                CP16(d + dstA[p], srcA[p] + ko);
                CP16(d + dstB[p], srcB[p] + ko);
            }
        }
        CP_COMMIT();

        const uint32_t so = sbase + stage * STAGE_BYTES;
#pragma unroll
        for (int kkk = 0; kkk < 4; kkk++) {  // four k16 substeps per 128B chunk
            uint32_t bf[4][4];
#pragma unroll
            for (int p = 0; p < 4; p++)      // B fragments: 64 rows (nt pairs)
                LDSM4(bf[p], so + bRB + p * 16 * 128 + bcs[kkk]);

            // A-fragment software pipeline: load a[mt+1] before a[mt]'s MMAs
            uint32_t a_cur[4], a_nxt[4];
            LDSM4(a_cur, so + aRB + acs[kkk]);
#pragma unroll
            for (int mt = 0; mt < 4; mt++) {
                if (mt < 3)
                    LDSM4(a_nxt, so + aRB + (mt + 1) * 16 * 128 + acs[kkk]);
#pragma unroll
                for (int nt = 0; nt < 8; nt++) {
                    uint32_t b0 = bf[nt >> 1][(nt & 1) * 2];
                    uint32_t b1 = bf[nt >> 1][(nt & 1) * 2 + 1];
                    MMAB16(acc[mt][nt], a_cur[0], a_cur[1], a_cur[2], a_cur[3], b0, b1);
                }
                if (mt < 3) {
                    a_cur[0] = a_nxt[0]; a_cur[1] = a_nxt[1];
                    a_cur[2] = a_nxt[2]; a_cur[3] = a_nxt[3];
                }
            }
        }
        if (++stage == NSTAGE) stage = 0;
    }

    // ---- epilogue (R14 proven) ----
    if (which == 0) {
        // fused SiLU: N-cols interleaved (even=gate_j, odd=up_j)
#pragma unroll
        for (int mt = 0; mt < 4; mt++) {
            int row = rowbase + wm * 64 + mt * 16 + g;
            float s0 = adq[row] * wrec;
            float s1 = adq[row + 8] * wrec;
            float* sr0 = g_s + (size_t)row * IDIM + (colbase >> 1) + wn * 32;
            float* sr1 = sr0 + (size_t)8 * IDIM;
#pragma unroll
            for (int nt = 0; nt < 8; nt++) {
                float gt0 = acc[mt][nt][0] * s0;
                float up0 = acc[mt][nt][1] * s0;
                float gt1 = acc[mt][nt][2] * s1;
                float up1 = acc[mt][nt][3] * s1;
                float sg0 = 1.0f / (1.0f + expf(-gt0));
                float sg1 = 1.0f / (1.0f + expf(-gt1));
                sr0[nt * 4 + tig] = (gt0 * sg0) * up0;
                sr1[nt * 4 + tig] = (gt1 * sg1) * up1;
            }
        }
    } else {
#pragma unroll
        for (int mt = 0; mt < 4; mt++) {
            int row = rowbase + wm * 64 + mt * 16 + g;
            float s0 = adq[row] * wrec;
            float s1 = adq[row + 8] * wrec;
            float* cr0 = outp + (size_t)row * N + colbase + wn * 64;
            float* cr1 = cr0 + (size_t)8 * N;
#pragma unroll
            for (int nt = 0; nt < 8; nt++) {
                float2 v0, v1;
                v0.x = acc[mt][nt][0] * s0;
                v0.y = acc[mt][nt][1] * s0;
                v1.x = acc[mt][nt][2] * s1;
                v1.y = acc[mt][nt][3] * s1;
                *reinterpret_cast<float2*>(cr0 + nt * 8 + tig * 2) = v0;
                *reinterpret_cast<float2*>(cr1 + nt * 8 + tig * 2) = v1;
            }
        }
    }
}

// ======================= launch =======================
extern "C" void kernel_launch(void* const* d_in, const int* in_sizes, int n_in,
                              void* d_out, int out_size) {
    const float* x      = (const float*)d_in[0];
    const float* w_gate = (const float*)d_in[1];
    const float* g_gate = (const float*)d_in[2];
    const float* w_down = (const float*)d_in[3];
    const float* g_down = (const float*)d_in[4];
    float* out = (float*)d_out;

    cudaFuncSetAttribute(k_gemm_mma, cudaFuncAttributeMaxDynamicSharedMemorySize, GEMM_SMEM);

    // launch indices: 0 abspart, 1 finalize, 2 quant_act, 3 GEMM1 (profiled), 4 actq2, 5 GEMM2
    k_abspart<<<6144, 256>>>(w_gate, w_down);
    k_finalize<<<1, 256>>>();
    k_quant_act<<<53248, 256>>>(w_gate, w_down, x, g_gate);
    k_gemm_mma<<<dim3(NGU / 128, MTOK / 128), 128, GEMM_SMEM>>>(0, nullptr);
    k_actq2<<<MTOK, 256>>>(g_down);
    k_gemm_mma<<<dim3(HDIM / 128, MTOK / 128), 128, GEMM_SMEM>>>(1, out);
}

// round 16
// speedup vs baseline: 1.0321x; 1.0321x over previous
#include <cuda_runtime.h>
#include <cuda_bf16.h>
#include <math.h>
#include <stdint.h>

// Problem dims (fixed by setup_inputs): B=2, S=2048, H=2048, I=8192
#define MTOK 4096
#define HDIM 2048
#define IDIM 8192
#define NGU  16384

// ---------------- scratch (static __device__ globals; device-side use ONLY) --------
__device__ double g_part1[4096];
__device__ double g_part2[2048];
__device__ float  g_consts[4];                           // {s1, 1/s1, s2, 1/s2}
__device__ __nv_bfloat16 g_w1q[(size_t)NGU  * HDIM];     // gate/up row-interleaved
__device__ __nv_bfloat16 g_w2q[(size_t)HDIM * IDIM];
__device__ __nv_bfloat16 g_a1q[(size_t)MTOK * HDIM];
__device__ __nv_bfloat16 g_a2q[(size_t)MTOK * IDIM];
__device__ float g_a1dq[MTOK];
__device__ float g_a2dq[MTOK];
__device__ float g_s[(size_t)MTOK * IDIM];               // silu(gate)*up, f32

__device__ __forceinline__ uint32_t s2u(const void* p) {
    uint32_t a;
    asm("{ .reg .u64 t; cvta.to.shared.u64 t, %1; cvt.u32.u64 %0, t; }" : "=r"(a) : "l"(p));
    return a;
}

#define MMAB16(c, a0, a1, a2, a3, b0, b1) \
    asm volatile("mma.sync.aligned.m16n8k16.row.col.f32.bf16.bf16.f32 " \
                 "{%0,%1,%2,%3}, {%4,%5,%6,%7}, {%8,%9}, {%0,%1,%2,%3};" \
                 : "+f"((c)[0]), "+f"((c)[1]), "+f"((c)[2]), "+f"((c)[3]) \
                 : "r"(a0), "r"(a1), "r"(a2), "r"(a3), "r"(b0), "r"(b1))

#define LDSM4(r, addr) \
    asm volatile("ldmatrix.sync.aligned.m8n8.x4.shared.b16 {%0,%1,%2,%3}, [%4];" \
                 : "=r"((r)[0]), "=r"((r)[1]), "=r"((r)[2]), "=r"((r)[3]) : "r"(addr))

#define CP16(dst, src) \
    asm volatile("cp.async.cg.shared.global [%0], [%1], 16;" \
                 :: "r"(dst), "l"(__cvta_generic_to_global(src)) : "memory")
#define CP_COMMIT() asm volatile("cp.async.commit_group;" ::: "memory")
#define CP_WAIT1()  asm volatile("cp.async.wait_group 1;" ::: "memory")

// ======================= elementwise kernels (proven) =======================
__global__ void k_abspart(const float* __restrict__ wg, const float* __restrict__ wd) {
    const float* w;
    double* part;
    int bi;
    if (blockIdx.x < 4096) { w = wg; part = g_part1; bi = blockIdx.x; }
    else                   { w = wd; part = g_part2; bi = blockIdx.x - 4096; }
    size_t base = (size_t)bi * 8192 + (size_t)threadIdx.x * 4;
    double acc = 0.0;
#pragma unroll
    for (int j = 0; j < 8; j++) {
        float4 v = *reinterpret_cast<const float4*>(w + base + (size_t)j * 1024);
        acc += (double)fabsf(v.x) + (double)fabsf(v.y) +
               (double)fabsf(v.z) + (double)fabsf(v.w);
    }
    __shared__ double sm[256];
    sm[threadIdx.x] = acc;
    __syncthreads();
    for (int s = 128; s > 0; s >>= 1) {
        if (threadIdx.x < s) sm[threadIdx.x] += sm[threadIdx.x + s];
        __syncthreads();
    }
    if (threadIdx.x == 0) part[bi] = sm[0];
}

__global__ void k_finalize() {
    __shared__ double sm[256];
    int t = threadIdx.x;
    double a = 0.0;
    for (int i = t; i < 4096; i += 256) a += g_part1[i];
    sm[t] = a; __syncthreads();
    for (int s = 128; s > 0; s >>= 1) { if (t < s) sm[t] += sm[t + s]; __syncthreads(); }
    double sum1 = sm[0];
    __syncthreads();
    double b = 0.0;
    for (int i = t; i < 2048; i += 256) b += g_part2[i];
    sm[t] = b; __syncthreads();
    for (int s = 128; s > 0; s >>= 1) { if (t < s) sm[t] += sm[t + s]; __syncthreads(); }
    if (t == 0) {
        float m1 = (float)(sum1 / (double)((size_t)NGU * HDIM));
        float s1 = 1.0f / fmaxf(m1, 1e-5f);
        g_consts[0] = s1; g_consts[1] = 1.0f / s1;
        float m2 = (float)(sm[0] / (double)((size_t)HDIM * IDIM));
        float s2 = 1.0f / fmaxf(m2, 1e-5f);
        g_consts[2] = s2; g_consts[3] = 1.0f / s2;
    }
}

// fused: blocks [0,49152) weight ternarization; [49152,53248) rmsnorm+actquant stage1
__global__ void k_quant_act(const float* __restrict__ wg, const float* __restrict__ wd,
                            const float* __restrict__ x,  const float* __restrict__ gg) {
    __shared__ float sm[256];
    const unsigned NBW = 49152;
    const unsigned NB1 = ((unsigned)NGU * HDIM) / 1024;   // 32768

    if (blockIdx.x < NBW) {
        const float* w;
        __nv_bfloat16* wq;
        float scale;
        size_t isrc, idst;
        if (blockIdx.x < NB1) {
            w = wg; wq = g_w1q; scale = g_consts[0];
            isrc = ((size_t)blockIdx.x * 256 + threadIdx.x) * 4;
            size_t row = isrc / HDIM;
            size_t col = isrc % HDIM;
            size_t drow = (row < IDIM) ? (2 * row) : (2 * (row - IDIM) + 1);
            idst = drow * HDIM + col;
        } else {
            w = wd; wq = g_w2q; scale = g_consts[2];
            isrc = ((size_t)(blockIdx.x - NB1) * 256 + threadIdx.x) * 4;
            idst = isrc;
        }
        float4 v = *reinterpret_cast<const float4*>(w + isrc);
        __nv_bfloat162 p0, p1;
        p0.x = __float2bfloat16(fminf(fmaxf(rintf(v.x * scale), -1.0f), 1.0f));
        p0.y = __float2bfloat16(fminf(fmaxf(rintf(v.y * scale), -1.0f), 1.0f));
        p1.x = __float2bfloat16(fminf(fmaxf(rintf(v.z * scale), -1.0f), 1.0f));
        p1.y = __float2bfloat16(fminf(fmaxf(rintf(v.w * scale), -1.0f), 1.0f));
        uint2 pk;
        pk.x = *reinterpret_cast<uint32_t*>(&p0);
        pk.y = *reinterpret_cast<uint32_t*>(&p1);
        *reinterpret_cast<uint2*>(wq + idst) = pk;
    } else {
        int m = blockIdx.x - NBW, t = threadIdx.x;
        const float* xr = x + (size_t)m * HDIM;
        float v[8]; float ss = 0.0f;
#pragma unroll
        for (int j = 0; j < 8; j++) { v[j] = xr[t + j * 256]; ss += v[j] * v[j]; }
        sm[t] = ss; __syncthreads();
        for (int s = 128; s > 0; s >>= 1) { if (t < s) sm[t] += sm[t + s]; __syncthreads(); }
        float var = sm[0] * (1.0f / (float)HDIM);
        __syncthreads();
        float r = 1.0f / sqrtf(var + 1e-8f);
        float h[8]; float am = 0.0f;
#pragma unroll
        for (int j = 0; j < 8; j++) {
            h[j] = (v[j] * r) * gg[t + j * 256];
            am = fmaxf(am, fabsf(h[j]));
        }
        sm[t] = am; __syncthreads();
        for (int s = 128; s > 0; s >>= 1) { if (t < s) sm[t] = fmaxf(sm[t], sm[t + s]); __syncthreads(); }
        float qs = 127.0f / fmaxf(sm[0], 1e-5f);
        __nv_bfloat16* aq = g_a1q + (size_t)m * HDIM;
#pragma unroll
        for (int j = 0; j < 8; j++) {
            float q = fminf(fmaxf(rintf(h[j] * qs), -128.0f), 127.0f);
            aq[t + j * 256] = __float2bfloat16(q);
        }
        if (t == 0) g_a1dq[m] = 1.0f / qs;
    }
}

// stage-2: reads precomputed s = silu(gate)*up; rmsnorm(g_down) + quant
__global__ void k_actq2(const float* __restrict__ gdown) {
    __shared__ float sm[256];
    int m = blockIdx.x, t = threadIdx.x;
    const float* sr = g_s + (size_t)m * IDIM;
    float s[32]; float ss = 0.0f;
#pragma unroll
    for (int j = 0; j < 32; j++) {
        float sv = sr[t + j * 256];
        s[j] = sv; ss += sv * sv;
    }
    sm[t] = ss; __syncthreads();
    for (int st = 128; st > 0; st >>= 1) { if (t < st) sm[t] += sm[t + st]; __syncthreads(); }
    float var = sm[0] * (1.0f / (float)IDIM);
    __syncthreads();
    float r = 1.0f / sqrtf(var + 1e-8f);
    float am = 0.0f;
#pragma unroll
    for (int j = 0; j < 32; j++) {
        s[j] = (s[j] * r) * gdown[t + j * 256];
        am = fmaxf(am, fabsf(s[j]));
    }
    sm[t] = am; __syncthreads();
    for (int st = 128; st > 0; st >>= 1) { if (t < st) sm[t] = fmaxf(sm[t], sm[t + st]); __syncthreads(); }
    float qs = 127.0f / fmaxf(sm[0], 1e-5f);
    __nv_bfloat16* aq = g_a2q + (size_t)m * IDIM;
#pragma unroll
    for (int j = 0; j < 32; j++) {
        float q = fminf(fmaxf(rintf(s[j] * qs), -128.0f), 127.0f);
        aq[t + j * 256] = __float2bfloat16(q);
    }
    if (t == 0) g_a2dq[m] = 1.0f / qs;
}

// ======================= bf16 HMMA GEMM v9: deferred refill ========================
// R14 body (proven: KCE=64 SW128, 128thr/CTA, 64x64 warp tiles, 2 CTAs/SM) with ONE
// change: the cp.async refill burst is issued AFTER substep 0's MMAs, not before —
// post-barrier the tensor pipe starts immediately and the LSU burst hides under
// substeps 1-3 (~768 tensor cycles).
#define KCE 64
#define TILE_BYTES 16384                    // 128 rows x 128B per operand
#define STAGE_BYTES (2 * TILE_BYTES)        // 32768
#define NSTAGE 3
#define GEMM_SMEM (NSTAGE * STAGE_BYTES)    // 98304

__global__ __launch_bounds__(128, 2) void k_gemm_mma(int which, float* __restrict__ outp) {
    const __nv_bfloat16* A;
    const __nv_bfloat16* W;
    const float* adq;
    float wrec;
    int N, K;
    if (which == 0) {
        A = g_a1q; W = g_w1q; adq = g_a1dq;
        wrec = g_consts[1]; N = NGU; K = HDIM;
    } else {
        A = g_a2q; W = g_w2q; adq = g_a2dq;
        wrec = g_consts[3]; N = HDIM; K = IDIM;
    }

    extern __shared__ __align__(16) char smbuf[];
    const uint32_t sbase = s2u(smbuf);

    const int tid  = threadIdx.x;
    const int lane = tid & 31;
    const int warp = tid >> 5;
    const int wm   = warp >> 1;             // 0..1 (M)
    const int wn   = warp & 1;              // 0..1 (N)
    const int g    = lane >> 2;
    const int tig  = lane & 3;
    const int rowbase = blockIdx.y * 128;
    const int colbase = blockIdx.x * 128;

    // ---- cp.async loader: 16 x 16B per thread per chunk (8 passes x A,B) ----
    const int lr8 = tid >> 3;               // 0..15 (row within pass)
    const int lc8 = tid & 7;                // 16B column 0..7
    uint32_t dstA[8], dstB[8];
    const __nv_bfloat16* srcA[8];
    const __nv_bfloat16* srcB[8];
#pragma unroll
    for (int p = 0; p < 8; p++) {
        int r = p * 16 + lr8;
        uint32_t off = (uint32_t)(r * 128 + ((lc8 ^ (r & 7)) * 16));
        dstA[p] = off;
        dstB[p] = TILE_BYTES + off;
        srcA[p] = A + (size_t)(rowbase + r) * K + lc8 * 8;
        srcB[p] = W + (size_t)(colbase + r) * K + lc8 * 8;
    }

    // ---- ldmatrix lane addressing (proven swizzle formulas) ----
    const uint32_t m8  = (uint32_t)(lane & 7);
    const uint32_t aRB = (uint32_t)((wm * 64 + (lane & 15)) * 128);
    const uint32_t ahi = (uint32_t)(lane >> 4);
    const uint32_t bRB = (uint32_t)(TILE_BYTES +
                          (wn * 64 + ((lane >> 4) & 1) * 8 + (lane & 7)) * 128);
    const uint32_t bhi = (uint32_t)((lane >> 3) & 1);

    uint32_t acs[4], bcs[4];
#pragma unroll
    for (int k = 0; k < 4; k++) {
        acs[k] = ((2u * k + ahi) ^ m8) * 16u;
        bcs[k] = ((2u * k + bhi) ^ m8) * 16u;
    }

    float acc[4][8][4];
#pragma unroll
    for (int i = 0; i < 4; i++)
#pragma unroll
        for (int j = 0; j < 8; j++)
#pragma unroll
            for (int q = 0; q < 4; q++) acc[i][j][q] = 0.0f;

    const int nk = K / KCE;

    // ---- prologue: stage chunks 0,1 ----
#pragma unroll
    for (int s = 0; s < 2; s++) {
        uint32_t d = sbase + s * STAGE_BYTES;
        int ko = s * KCE;
#pragma unroll
        for (int p = 0; p < 8; p++) {
            CP16(d + dstA[p], srcA[p] + ko);
            CP16(d + dstB[p], srcB[p] + ko);
        }
        CP_COMMIT();
    }

    int stage = 0;
    for (int kt = 0; kt < nk; kt++) {
        CP_WAIT1();
        __syncthreads();

        const uint32_t so = sbase + stage * STAGE_BYTES;

        // ---- substep 0 FIRST: tensor pipe starts immediately post-barrier ----
        {
            uint32_t bf[4][4];
#pragma unroll
            for (int p = 0; p < 4; p++)
                LDSM4(bf[p], so + bRB + p * 16 * 128 + bcs[0]);
#pragma unroll
            for (int mt = 0; mt < 4; mt++) {
                uint32_t a[4];
                LDSM4(a, so + aRB + mt * 16 * 128 + acs[0]);
#pragma unroll
                for (int nt = 0; nt < 8; nt++) {
                    uint32_t b0 = bf[nt >> 1][(nt & 1) * 2];
                    uint32_t b1 = bf[nt >> 1][(nt & 1) * 2 + 1];
                    MMAB16(acc[mt][nt], a[0], a[1], a[2], a[3], b0, b1);
                }
            }
        }

        // ---- deferred refill: issues in the shadow of substeps 1-3 ----
        if (kt + 2 < nk) {
            int rs = stage + 2; if (rs >= NSTAGE) rs -= NSTAGE;
            uint32_t d = sbase + rs * STAGE_BYTES;
            int ko = (kt + 2) * KCE;
#pragma unroll
            for (int p = 0; p < 8; p++) {
                CP16(d + dstA[p], srcA[p] + ko);
                CP16(d + dstB[p], srcB[p] + ko);
            }
        }
        CP_COMMIT();

        // ---- substeps 1..3 ----
#pragma unroll
        for (int kkk = 1; kkk < 4; kkk++) {
            uint32_t bf[4][4];
#pragma unroll
            for (int p = 0; p < 4; p++)
                LDSM4(bf[p], so + bRB + p * 16 * 128 + bcs[kkk]);
#pragma unroll
            for (int mt = 0; mt < 4; mt++) {
                uint32_t a[4];
                LDSM4(a, so + aRB + mt * 16 * 128 + acs[kkk]);
#pragma unroll
                for (int nt = 0; nt < 8; nt++) {
                    uint32_t b0 = bf[nt >> 1][(nt & 1) * 2];
                    uint32_t b1 = bf[nt >> 1][(nt & 1) * 2 + 1];
                    MMAB16(acc[mt][nt], a[0], a[1], a[2], a[3], b0, b1);
                }
            }
        }
        if (++stage == NSTAGE) stage = 0;
    }

    // ---- epilogue ----
    if (which == 0) {
        // fused SiLU: N-cols interleaved (even=gate_j, odd=up_j); __expf (MUFU)
#pragma unroll
        for (int mt = 0; mt < 4; mt++) {
            int row = rowbase + wm * 64 + mt * 16 + g;
            float s0 = adq[row] * wrec;
            float s1 = adq[row + 8] * wrec;
            float* sr0 = g_s + (size_t)row * IDIM + (colbase >> 1) + wn * 32;
            float* sr1 = sr0 + (size_t)8 * IDIM;
#pragma unroll
            for (int nt = 0; nt < 8; nt++) {
                float gt0 = acc[mt][nt][0] * s0;
                float up0 = acc[mt][nt][1] * s0;
                float gt1 = acc[mt][nt][2] * s1;
                float up1 = acc[mt][nt][3] * s1;
                float sg0 = 1.0f / (1.0f + __expf(-gt0));
                float sg1 = 1.0f / (1.0f + __expf(-gt1));
                sr0[nt * 4 + tig] = (gt0 * sg0) * up0;
                sr1[nt * 4 + tig] = (gt1 * sg1) * up1;
            }
        }
    } else {
#pragma unroll
        for (int mt = 0; mt < 4; mt++) {
            int row = rowbase + wm * 64 + mt * 16 + g;
            float s0 = adq[row] * wrec;
            float s1 = adq[row + 8] * wrec;
            float* cr0 = outp + (size_t)row * N + colbase + wn * 64;
            float* cr1 = cr0 + (size_t)8 * N;
#pragma unroll
            for (int nt = 0; nt < 8; nt++) {
                float2 v0, v1;
                v0.x = acc[mt][nt][0] * s0;
                v0.y = acc[mt][nt][1] * s0;
                v1.x = acc[mt][nt][2] * s1;
                v1.y = acc[mt][nt][3] * s1;
                *reinterpret_cast<float2*>(cr0 + nt * 8 + tig * 2) = v0;
                *reinterpret_cast<float2*>(cr1 + nt * 8 + tig * 2) = v1;
            }
        }
    }
}

// ======================= launch =======================
extern "C" void kernel_launch(void* const* d_in, const int* in_sizes, int n_in,
                              void* d_out, int out_size) {
    const float* x      = (const float*)d_in[0];
    const float* w_gate = (const float*)d_in[1];
    const float* g_gate = (const float*)d_in[2];
    const float* w_down = (const float*)d_in[3];
    const float* g_down = (const float*)d_in[4];
    float* out = (float*)d_out;

    cudaFuncSetAttribute(k_gemm_mma, cudaFuncAttributeMaxDynamicSharedMemorySize, GEMM_SMEM);

    // launch indices: 0 abspart, 1 finalize, 2 quant_act, 3 GEMM1 (profiled), 4 actq2, 5 GEMM2
    k_abspart<<<6144, 256>>>(w_gate, w_down);
    k_finalize<<<1, 256>>>();
    k_quant_act<<<53248, 256>>>(w_gate, w_down, x, g_gate);
    k_gemm_mma<<<dim3(NGU / 128, MTOK / 128), 128, GEMM_SMEM>>>(0, nullptr);
    k_actq2<<<MTOK, 256>>>(g_down);
    k_gemm_mma<<<dim3(HDIM / 128, MTOK / 128), 128, GEMM_SMEM>>>(1, out);
}